// round 15
// baseline (speedup 1.0000x reference)
#include <cuda_runtime.h>
#include <cuda_fp16.h>
#include <cstdint>

#define NB 8
#define CDIM 512
#define NHEADS 8
#define HD 64
#define NT 4096           // H*W = 64*64

// ---------------- scratch (device globals: alloc-free) ----------------
// g_qkvo: q,k channels ONLY (c in [0,1024)), fp32, elu(.)+1 already applied.
// g_vg:   v,gate channels (original c in [1024,2048)), fp16 raw (bias applied).
__device__ float  g_qkvo[(size_t)NB * 1024 * NT];   // 134 MB fp32 (q,k elu'd)
__device__ __half g_vg  [(size_t)NB * 1024 * NT];   // 67 MB fp16 (v, gate)
__device__ __half g_lepe[(size_t)NB * CDIM * NT];   // 33 MB fp16
__device__ float  g_eff [NB * NHEADS * NT];
__device__ float  g_kv  [NB * NHEADS * HD * HD];
__device__ float  g_km  [NB * NHEADS * HD];
__device__ float  g_qm  [NB * NHEADS * HD];
// transposed rope tables [d][t] for coalesced access in kv/res
__device__ float  g_sint[HD * NT];                  // 1 MB
__device__ float  g_cost[HD * NT];                  // 1 MB

// fp16 operand buffers for tensor-core GEMMs (single product, pure fp16)
__device__ __half g_wqh[2048 * 512];
__device__ __half g_wph[512 * 512];
__device__ __half g_xth[(size_t)NB * NT * 512];
__device__ __half g_yth[(size_t)NB * NT * 512];

__device__ __forceinline__ float elu1(float x) { return x > 0.f ? x + 1.f : __expf(x); }

__device__ __forceinline__ float warpSum(float v) {
#pragma unroll
    for (int o = 16; o > 0; o >>= 1) v += __shfl_xor_sync(0xffffffffu, v, o);
    return v;
}
__device__ __forceinline__ float warpMax(float v) {
#pragma unroll
    for (int o = 16; o > 0; o >>= 1) v = fmaxf(v, __shfl_xor_sync(0xffffffffu, v, o));
    return v;
}

__device__ __forceinline__ uint32_t smem_u32(const void* p) {
    uint32_t a;
    asm("{ .reg .u64 t; cvta.to.shared.u64 t, %1; cvt.u32.u64 %0, t; }" : "=r"(a) : "l"(p));
    return a;
}
__device__ __forceinline__ void cp_async16(uint32_t dst, const void* src) {
    asm volatile("cp.async.cg.shared.global [%0], [%1], 16;" :: "r"(dst), "l"(src) : "memory");
}
__device__ __forceinline__ void cp_commit() {
    asm volatile("cp.async.commit_group;" ::: "memory");
}
template <int N>
__device__ __forceinline__ void cp_wait() {
    asm volatile("cp.async.wait_group %0;" :: "n"(N) : "memory");
}
__device__ __forceinline__ void ldsm_x4(uint32_t* r, uint32_t addr) {
    asm volatile("ldmatrix.sync.aligned.m8n8.x4.shared.b16 {%0,%1,%2,%3}, [%4];"
                 : "=r"(r[0]), "=r"(r[1]), "=r"(r[2]), "=r"(r[3]) : "r"(addr));
}
__device__ __forceinline__ void mma16816(float* d, const uint32_t* a, uint32_t b0, uint32_t b1) {
    asm volatile("mma.sync.aligned.m16n8k16.row.col.f32.f16.f16.f32 "
                 "{%0,%1,%2,%3}, {%4,%5,%6,%7}, {%8,%9}, {%0,%1,%2,%3};"
                 : "+f"(d[0]), "+f"(d[1]), "+f"(d[2]), "+f"(d[3])
                 : "r"(a[0]), "r"(a[1]), "r"(a[2]), "r"(a[3]), "r"(b0), "r"(b1));
}

// ---------------- zero accumulators (must run every graph replay) ----------------
__global__ void zero_kernel() {
    int i = blockIdx.x * blockDim.x + threadIdx.x;
    if (i < NB * NHEADS * HD * HD) g_kv[i] = 0.f;
    if (i < NB * NHEADS * HD) { g_km[i] = 0.f; g_qm[i] = 0.f; }
}

// ---------------- weight convert: fp32 -> fp16 ----------------
__global__ void wconv_kernel(const float* __restrict__ w, __half* __restrict__ wh, int n)
{
    int i = blockIdx.x * 256 + threadIdx.x;
    if (i < n) wh[i] = __float2half(w[i]);
}

// ---------------- sin/cos transpose: [t][d] -> [d][t] (coalesced rope reads) ----------------
__global__ void __launch_bounds__(256) scT_kernel(
    const float* __restrict__ sinp, const float* __restrict__ cosp)
{
    __shared__ float ts[32][33], tc[32][33];
    const int t0 = blockIdx.x * 32, d0 = blockIdx.y * 32;
    const int tx = threadIdx.x & 31, ty = threadIdx.x >> 5;   // 32x8
#pragma unroll
    for (int i = 0; i < 32; i += 8) {
        ts[ty + i][tx] = sinp[(size_t)(t0 + ty + i) * 64 + d0 + tx];
        tc[ty + i][tx] = cosp[(size_t)(t0 + ty + i) * 64 + d0 + tx];
    }
    __syncthreads();
#pragma unroll
    for (int i = 0; i < 32; i += 8) {
        g_sint[(size_t)(d0 + ty + i) * NT + t0 + tx] = ts[tx][ty + i];
        g_cost[(size_t)(d0 + ty + i) * NT + t0 + tx] = tc[tx][ty + i];
    }
}

// ---------------- transpose-convert: x[b][k][n] fp32 -> xT[b][n][k] fp16 ----------------
__global__ void __launch_bounds__(256) xpose_kernel(const float* __restrict__ x)
{
    const int b = blockIdx.z;
    const float* src = x + (size_t)b * 512 * NT;
    __half* dh = g_xth + (size_t)b * NT * 512;
    __shared__ float tile[32][33];
    const int n0 = blockIdx.x * 32, k0 = blockIdx.y * 32;
    const int tx = threadIdx.x & 31, ty = threadIdx.x >> 5; // 32x8
#pragma unroll
    for (int i = 0; i < 32; i += 8)
        tile[ty + i][tx] = src[(size_t)(k0 + ty + i) * NT + n0 + tx];
    __syncthreads();
#pragma unroll
    for (int i = 0; i < 32; i += 8) {
        size_t o = (size_t)(n0 + ty + i) * 512 + k0 + tx;
        dh[o] = __float2half(tile[tx][ty + i]);
    }
}

// ---------------- HMMA GEMM: C = A @ B^T + bias (BK=32, R11 best) ----------------
#define SROW 40
#define ARR_BYTES (128 * SROW * 2)     // 10240
#define STAGE_BYTES (2 * ARR_BYTES)    // 20480
#define GEMM_SMEM (2 * STAGE_BYTES)    // 40960

__global__ void __launch_bounds__(256, 2) gemm_hmma_kernel(
    const __half* __restrict__ Ah, const __half* __restrict__ Bh,
    const float* __restrict__ bias, float* __restrict__ C, __half* __restrict__ C16,
    int N, int elu_rows, int c16_start, int c_rows)
{
    const int b = blockIdx.z;
    const int m0 = blockIdx.y * 128, n0 = blockIdx.x * 128;
    const __half* pAh = Ah + (size_t)m0 * 512;
    const __half* pBh = Bh + ((size_t)b * N + n0) * 512;
    float*  Cb  = C   + (size_t)b * c_rows * N;   // fp32 rows [0, c16_start)
    __half* C16b = C16 ? C16 + (size_t)b * 1024 * N : (__half*)0;

    extern __shared__ char smem[];
    const uint32_t sb = smem_u32(smem);

    const int tid = threadIdx.x;
    const int lane = tid & 31, wid = tid >> 5;
    const int warp_m = wid & 3, warp_n = wid >> 2;   // 4 x 2 warps -> 32 x 64 per warp

    // cp.async mapping: thread -> (row, half)
    const int lrow = tid >> 1, lhalf = tid & 1;
    const size_t goff = (size_t)lrow * 512 + lhalf * 16;            // elements
    const uint32_t soff = (uint32_t)(lrow * SROW + lhalf * 16) * 2; // bytes

    // ldmatrix per-lane offsets (A and B both non-trans: SMEM is [row][k])
    const int arow = ((lane >> 3) & 1) * 8 + (lane & 7);   // = lane % 16
    const int acol = (lane >> 4) * 8;                      // k element offset
    const int brow = ((lane >> 4) & 1) * 8 + (lane & 7);   // n row within 16
    const int bcol = ((lane >> 3) & 1) * 8;                // k element offset

    float acc[2][8][4];
#pragma unroll
    for (int i = 0; i < 2; i++)
#pragma unroll
        for (int j = 0; j < 8; j++)
#pragma unroll
            for (int q = 0; q < 4; q++) acc[i][j][q] = 0.f;

    // prologue: stage 0
    {
        uint32_t d = sb + soff;
        cp_async16(d + 0 * ARR_BYTES, pAh + goff);
        cp_async16(d + 0 * ARR_BYTES + 16, pAh + goff + 8);
        cp_async16(d + 1 * ARR_BYTES, pBh + goff);
        cp_async16(d + 1 * ARR_BYTES + 16, pBh + goff + 8);
        cp_commit();
    }

    for (int c = 0; c < 16; c++) {
        cp_wait<0>();
        __syncthreads();

        if (c + 1 < 16) {     // issue next chunk; overlaps with compute of chunk c
            const size_t g = goff + (c + 1) * 32;
            uint32_t d = sb + ((c + 1) & 1) * STAGE_BYTES + soff;
            cp_async16(d + 0 * ARR_BYTES, pAh + g);
            cp_async16(d + 0 * ARR_BYTES + 16, pAh + g + 8);
            cp_async16(d + 1 * ARR_BYTES, pBh + g);
            cp_async16(d + 1 * ARR_BYTES + 16, pBh + g + 8);
            cp_commit();
        }

        const uint32_t st = sb + (c & 1) * STAGE_BYTES;
        const uint32_t aB  = st + 0 * ARR_BYTES;  // A
        const uint32_t bB  = st + 1 * ARR_BYTES;  // B

#pragma unroll
        for (int kk = 0; kk < 2; kk++) {
            uint32_t ah[2][4];
#pragma unroll
            for (int mt = 0; mt < 2; mt++) {
                uint32_t ao = (uint32_t)((warp_m * 32 + mt * 16 + arow) * SROW + kk * 16 + acol) * 2;
                ldsm_x4(ah[mt], aB + ao);
            }
#pragma unroll
            for (int g = 0; g < 4; g++) {
                uint32_t bo = (uint32_t)((warp_n * 64 + g * 16 + brow) * SROW + kk * 16 + bcol) * 2;
                uint32_t bh[4];
                ldsm_x4(bh, bB + bo);   // non-trans: SMEM already [n][k] (col-major B)
#pragma unroll
                for (int mt = 0; mt < 2; mt++) {
                    mma16816(acc[mt][g * 2 + 0], ah[mt], bh[0], bh[1]);
                    mma16816(acc[mt][g * 2 + 1], ah[mt], bh[2], bh[3]);
                }
            }
        }
        __syncthreads();   // protect stage (c&1) before it is re-filled at c+1
    }

    // epilogue: bias (+ fused elu + fused qmean) + fp32/fp16 stores
#pragma unroll
    for (int mt = 0; mt < 2; mt++) {
        int mA = m0 + warp_m * 32 + mt * 16 + (lane >> 2);
        int mB = mA + 8;
        float bv0 = bias[mA], bv1 = bias[mB];
        const bool e0r = mA < elu_rows, e1r = mB < elu_rows;
        const bool f0 = mA >= c16_start, f1 = mB >= c16_start;
        float*  r0f = Cb + (size_t)mA * N;
        float*  r1f = Cb + (size_t)mB * N;
        __half* r0h = f0 ? C16b + (size_t)(mA - c16_start) * N : (__half*)0;
        __half* r1h = f1 ? C16b + (size_t)(mB - c16_start) * N : (__half*)0;
        float qs0 = 0.f, qs1 = 0.f;
#pragma unroll
        for (int nt = 0; nt < 8; nt++) {
            int n = n0 + warp_n * 64 + nt * 8 + (lane & 3) * 2;
            float a0 = acc[mt][nt][0] + bv0, a1 = acc[mt][nt][1] + bv0;
            float a2 = acc[mt][nt][2] + bv1, a3 = acc[mt][nt][3] + bv1;
            if (e0r) { a0 = elu1(a0); a1 = elu1(a1); qs0 += a0 + a1; }
            if (e1r) { a2 = elu1(a2); a3 = elu1(a3); qs1 += a2 + a3; }
            if (f0) *(__half2*)(r0h + n) = __floats2half2_rn(a0, a1);
            else    *(float2*)(r0f + n) = make_float2(a0, a1);
            if (f1) *(__half2*)(r1h + n) = __floats2half2_rn(a2, a3);
            else    *(float2*)(r1f + n) = make_float2(a2, a3);
        }
        // fused qmean: q rows are m < 512 (only relevant for GEMM1, elu_rows > 0)
        if (elu_rows > 0 && mA < 512) {          // uniform across warp
            qs0 += __shfl_xor_sync(0xffffffffu, qs0, 1);
            qs0 += __shfl_xor_sync(0xffffffffu, qs0, 2);
            qs1 += __shfl_xor_sync(0xffffffffu, qs1, 1);
            qs1 += __shfl_xor_sync(0xffffffffu, qs1, 2);
            if ((lane & 3) == 0) {
                atomicAdd(&g_qm[(size_t)b * 512 + mA], qs0);
                atomicAdd(&g_qm[(size_t)b * 512 + mB], qs1);
            }
        }
    }
}

// ---------------- depthwise 5x5 conv on v channels (fp16) -> g_lepe (fp16) ----------------
__global__ void __launch_bounds__(256) conv_kernel(
    const float* __restrict__ w_lepe, const float* __restrict__ b_lepe)
{
    const int bc = blockIdx.x;
    const int b = bc >> 9, c = bc & 511;
    __shared__ float wsh[25];
    const int tid = threadIdx.x;
    if (tid < 25) wsh[tid] = w_lepe[c * 25 + tid];
    __syncthreads();

    const int y = blockIdx.y * 4 + (tid >> 6);
    const int xw = tid & 63;
    const __half* Vp = g_vg + ((size_t)b * 1024 + c) * NT;   // v channels = c' in [0,512)

    float acc = b_lepe[c];
#pragma unroll
    for (int i = 0; i < 5; i++) {
        int yy = y + i - 2;
        if (yy < 0 || yy >= 64) continue;
#pragma unroll
        for (int j = 0; j < 5; j++) {
            int xx = xw + j - 2;
            if (xx < 0 || xx >= 64) continue;
            acc += wsh[i * 5 + j] * __half2float(Vp[yy * 64 + xx]);
        }
    }
    g_lepe[((size_t)b * 512 + c) * NT + y * 64 + xw] = __float2half(acc);
}

// ---------------- logits -> softmax ----------------
__global__ void __launch_bounds__(256) logits_kernel()
{
    const int bh = blockIdx.x;
    const int b = bh >> 3, h = bh & 7;
    const float* Kp = g_qkvo + ((size_t)b * 1024 + 512 + h * 64) * NT;
    __shared__ float sq[64];
    const int tid = threadIdx.x;
    if (tid < 64) sq[tid] = g_qm[bh * 64 + tid] * (1.f / NT);
    __syncthreads();
    const int t = blockIdx.y * 256 + tid;
    float l = 0.f;
#pragma unroll 8
    for (int d = 0; d < 64; d++) l += sq[d] * Kp[(size_t)d * NT + t];
    g_eff[bh * NT + t] = l * 0.125f;   // SCALE
}

__global__ void __launch_bounds__(256) softmax_kernel()
{
    const int bh = blockIdx.x;
    const int tid = threadIdx.x;
    const int lane = tid & 31, wid = tid >> 5;
    __shared__ float red[8];
    float l[16];
#pragma unroll
    for (int i = 0; i < 16; i++) l[i] = g_eff[bh * NT + tid + i * 256];
    float mx = -1e30f;
#pragma unroll
    for (int i = 0; i < 16; i++) mx = fmaxf(mx, l[i]);
    mx = warpMax(mx);
    if (lane == 0) red[wid] = mx;
    __syncthreads();
    if (tid == 0) { float m = red[0]; for (int w = 1; w < 8; w++) m = fmaxf(m, red[w]); red[0] = m; }
    __syncthreads();
    mx = red[0];
    __syncthreads();
    float s = 0.f;
#pragma unroll
    for (int i = 0; i < 16; i++) s += __expf(l[i] - mx);
    s = warpSum(s);
    if (lane == 0) red[wid] = s;
    __syncthreads();
    if (tid == 0) { float ss = 0.f; for (int w = 0; w < 8; w++) ss += red[w]; red[0] = ss; }
    __syncthreads();
    const float inv = 1.f / red[0];
#pragma unroll
    for (int i = 0; i < 16; i++)
        g_eff[bh * NT + tid + i * 256] = __expf(l[i] - mx) * inv;
}

// ---------------- kv[d,e] = sum_t rope(k*eff)[t,d]*v[t,e];  km[d] = sum_t k*eff ----------------
// rope tables read from TRANSPOSED layout [d][t] -> coalesced.
__global__ void __launch_bounds__(256) kv_kernel()
{
    const int bh = blockIdx.x;
    const int b = bh >> 3, h = bh & 7;
    const int chunk = blockIdx.y;   // 16 chunks of 256 t
    const float*  Kp = g_qkvo + ((size_t)b * 1024 + 512 + h * 64) * NT;   // elu'd k
    const __half* Vp = g_vg   + ((size_t)b * 1024 + h * 64) * NT;         // v fp16
    const float* eff = g_eff + bh * NT;

    __shared__ float sk[64][65];   // rope(k*eff), [t][d]
    __shared__ float sv[64][65];   // v, [t][e]

    const int tid = threadIdx.x;
    const int ttl = tid & 63;
    const int drow = tid >> 6;     // 0..3
    const int d0 = (tid & 15) * 4, e0 = (tid >> 4) * 4;

    float acc[4][4];
#pragma unroll
    for (int i = 0; i < 4; i++)
#pragma unroll
        for (int j = 0; j < 4; j++) acc[i][j] = 0.f;
    float kmp[16];
#pragma unroll
    for (int i = 0; i < 16; i++) kmp[i] = 0.f;

    for (int tile = 0; tile < 4; tile++) {
        const int t = chunk * 256 + tile * 64 + ttl;
        const float effv = eff[t];
#pragma unroll
        for (int r = 0; r < 8; r++) {
            const int d = 2 * (drow + r * 4);
            float a  = Kp[(size_t)d * NT + t] * effv;
            float bb = Kp[(size_t)(d + 1) * NT + t] * effv;
            kmp[2 * r]     += a;
            kmp[2 * r + 1] += bb;
            float c0 = g_cost[(size_t)d * NT + t],       s0 = g_sint[(size_t)d * NT + t];
            float c1 = g_cost[(size_t)(d + 1) * NT + t], s1 = g_sint[(size_t)(d + 1) * NT + t];
            sk[ttl][d]     = a * c0 - bb * s0;
            sk[ttl][d + 1] = bb * c1 + a * s1;
            sv[ttl][d]     = __half2float(Vp[(size_t)d * NT + t]);
            sv[ttl][d + 1] = __half2float(Vp[(size_t)(d + 1) * NT + t]);
        }
        __syncthreads();

#pragma unroll 4
        for (int tt = 0; tt < 64; tt++) {
            float kk[4], vv[4];
#pragma unroll
            for (int j = 0; j < 4; j++) { kk[j] = sk[tt][d0 + j]; vv[j] = sv[tt][e0 + j]; }
#pragma unroll
            for (int i = 0; i < 4; i++)
#pragma unroll
                for (int j = 0; j < 4; j++) acc[i][j] += kk[i] * vv[j];
        }
        __syncthreads();
    }

    float* kvout = g_kv + (size_t)bh * HD * HD;
#pragma unroll
    for (int i = 0; i < 4; i++)
#pragma unroll
        for (int j = 0; j < 4; j++)
            atomicAdd(&kvout[(d0 + i) * 64 + e0 + j], acc[i][j]);

    // km reduction: stage register partials into sk, column-sum over t-slots
#pragma unroll
    for (int r = 0; r < 8; r++) {
        const int d = 2 * (drow + r * 4);
        sk[ttl][d]     = kmp[2 * r];
        sk[ttl][d + 1] = kmp[2 * r + 1];
    }
    __syncthreads();
    if (tid < 64) {
        float s = 0.f;
#pragma unroll 8
        for (int tt = 0; tt < 64; tt++) s += sk[tt][tid];
        atomicAdd(&g_km[bh * 64 + tid], s);
    }
}

// ---------------- res: y = (attn*z + lepe)*gate -> yT fp16 ----------------
// t-blocked (2 t x 32 e per thread): kv-row float4 LDS shared across both t
// => per-thread LDS.128 halved (1024 -> 512). Rope/q/gate loads coalesced.
__global__ void __launch_bounds__(256) res_kernel()
{
    const int bh = blockIdx.x;
    const int b = bh >> 3, h = bh & 7;
    const int tid = threadIdx.x;
    const int tl = tid & 127;
    const int eg = tid >> 7;                    // 0/1: e in [eg*32, eg*32+32)
    const int t0 = blockIdx.y * 256;
    const int tA = t0 + tl, tB = t0 + tl + 128;
    const float* Q = g_qkvo + ((size_t)b * 1024 + h * 64) * NT;   // elu'd q

    __shared__ float skv[64][64];
    __shared__ float skm[64];
#pragma unroll
    for (int r = 0; r < 16; r++)
        ((float*)skv)[tid + r * 256] = g_kv[(size_t)bh * 4096 + tid + r * 256];
    if (tid < 64) skm[tid] = g_km[bh * 64 + tid];
    __syncthreads();

    float resA[32], resB[32];
#pragma unroll
    for (int e = 0; e < 32; e++) { resA[e] = 0.f; resB[e] = 0.f; }
    float zA = 0.f, zB = 0.f;

    for (int p = 0; p < 32; p++) {
        const int d = 2 * p;
        float qA0 = Q[(size_t)d * NT + tA];
        float qA1 = Q[(size_t)(d + 1) * NT + tA];
        float qB0 = Q[(size_t)d * NT + tB];
        float qB1 = Q[(size_t)(d + 1) * NT + tB];
        zA += qA0 * skm[d] + qA1 * skm[d + 1];
        zB += qB0 * skm[d] + qB1 * skm[d + 1];
        float cA0 = g_cost[(size_t)d * NT + tA],       sA0 = g_sint[(size_t)d * NT + tA];
        float cA1 = g_cost[(size_t)(d + 1) * NT + tA], sA1 = g_sint[(size_t)(d + 1) * NT + tA];
        float cB0 = g_cost[(size_t)d * NT + tB],       sB0 = g_sint[(size_t)d * NT + tB];
        float cB1 = g_cost[(size_t)(d + 1) * NT + tB], sB1 = g_sint[(size_t)(d + 1) * NT + tB];
        float qrA0 = qA0 * cA0 - qA1 * sA0;
        float qrA1 = qA1 * cA1 + qA0 * sA1;
        float qrB0 = qB0 * cB0 - qB1 * sB0;
        float qrB1 = qB1 * cB1 + qB0 * sB1;
        const float4* kv0 = (const float4*)skv[d] + eg * 8;
        const float4* kv1 = (const float4*)skv[d + 1] + eg * 8;
#pragma unroll
        for (int e4 = 0; e4 < 8; e4++) {
            float4 a = kv0[e4], bb = kv1[e4];
            resA[e4 * 4 + 0] += qrA0 * a.x + qrA1 * bb.x;
            resA[e4 * 4 + 1] += qrA0 * a.y + qrA1 * bb.y;
            resA[e4 * 4 + 2] += qrA0 * a.z + qrA1 * bb.z;
            resA[e4 * 4 + 3] += qrA0 * a.w + qrA1 * bb.w;
            resB[e4 * 4 + 0] += qrB0 * a.x + qrB1 * bb.x;
            resB[e4 * 4 + 1] += qrB0 * a.y + qrB1 * bb.y;
            resB[e4 * 4 + 2] += qrB0 * a.z + qrB1 * bb.z;
            resB[e4 * 4 + 3] += qrB0 * a.w + qrB1 * bb.w;
        }
    }
    zA = 1.f / (zA + 1e-6f);
    zB = 1.f / (zB + 1e-6f);

    const size_t yrowA = ((size_t)b * NT + tA) * 512 + h * 64 + eg * 32;
    const size_t yrowB = ((size_t)b * NT + tB) * 512 + h * 64 + eg * 32;
#pragma unroll 8
    for (int e = 0; e < 32; e++) {
        int c = h * 64 + eg * 32 + e;
        const size_t gbase = ((size_t)b * 1024 + 512 + c) * NT;
        const size_t lbase = ((size_t)b * 512 + c) * NT;
        float gateA = __half2float(g_vg[gbase + tA]);
        float lepA  = __half2float(g_lepe[lbase + tA]);
        g_yth[yrowA + e] = __float2half((resA[e] * zA + lepA) * gateA);
        float gateB = __half2float(g_vg[gbase + tB]);
        float lepB  = __half2float(g_lepe[lbase + tB]);
        g_yth[yrowB + e] = __float2half((resB[e] * zB + lepB) * gateB);
    }
}

// ---------------- launch (single stream; GEMM1 at profiled slot #4) ----------------
extern "C" void kernel_launch(void* const* d_in, const int* in_sizes, int n_in,
                              void* d_out, int out_size)
{
    const float* x      = (const float*)d_in[0];
    const float* sinp   = (const float*)d_in[1];
    const float* cosp   = (const float*)d_in[2];
    const float* w_qkvo = (const float*)d_in[3];
    const float* b_qkvo = (const float*)d_in[4];
    const float* w_lepe = (const float*)d_in[5];
    const float* b_lepe = (const float*)d_in[6];
    const float* w_proj = (const float*)d_in[7];
    const float* b_proj = (const float*)d_in[8];
    float* out = (float*)d_out;

    float *qkvo_p = nullptr;
    __half *vg_p, *wqh, *wph, *xth, *yth;
    cudaGetSymbolAddress((void**)&qkvo_p, g_qkvo);
    cudaGetSymbolAddress((void**)&vg_p,  g_vg);
    cudaGetSymbolAddress((void**)&wqh, g_wqh);
    cudaGetSymbolAddress((void**)&wph, g_wph);
    cudaGetSymbolAddress((void**)&xth, g_xth);
    cudaGetSymbolAddress((void**)&yth, g_yth);

    cudaFuncSetAttribute(gemm_hmma_kernel, cudaFuncAttributeMaxDynamicSharedMemorySize, GEMM_SMEM);

    // launches 1-3 (profiler captures launch #4 = GEMM1)
    xpose_kernel<<<dim3(NT / 32, 512 / 32, NB), 256>>>(x);
    zero_kernel<<<(NB * NHEADS * HD * HD + 255) / 256, 256>>>();
    wconv_kernel<<<(2048 * 512 + 255) / 256, 256>>>(w_qkvo, wqh, 2048 * 512);

    // GEMM1 (launch #4): 2048 rows; m<1024 fp32+elu (q,k; qmean for m<512),
    // m>=1024 fp16 into g_vg (v, gate)
    gemm_hmma_kernel<<<dim3(NT / 128, 2048 / 128, NB), 256, GEMM_SMEM>>>(
        wqh, xth, b_qkvo, qkvo_p, vg_p, NT, 1024, 1024, 1024);

    scT_kernel<<<dim3(NT / 32, 2), 256>>>(sinp, cosp);   // rope tables -> [d][t]

    conv_kernel<<<dim3(NB * CDIM, 16), 256>>>(w_lepe, b_lepe);
    logits_kernel<<<dim3(NB * NHEADS, 16), 256>>>();
    softmax_kernel<<<NB * NHEADS, 256>>>();
    kv_kernel<<<dim3(NB * NHEADS, 16), 256>>>();
    res_kernel<<<dim3(NB * NHEADS, 16), 256>>>();

    wconv_kernel<<<(512 * 512 + 255) / 256, 256>>>(w_proj, wph, 512 * 512);

    // GEMM2: 512 rows, all fp32 to out; no elu/qmean/fp16
    gemm_hmma_kernel<<<dim3(NT / 128, 512 / 128, NB), 256, GEMM_SMEM>>>(
        wph, yth, b_proj, out, (__half*)0, NT, 0, 1 << 30, 512);
}

// round 16
// speedup vs baseline: 1.2829x; 1.2829x over previous
#include <cuda_runtime.h>
#include <cuda_fp16.h>
#include <cstdint>

#define NB 8
#define CDIM 512
#define NHEADS 8
#define HD 64
#define NT 4096           // H*W = 64*64

// ---------------- scratch (device globals: alloc-free) ----------------
// g_qkvo: q,k channels ONLY (c in [0,1024)), fp32, elu(.)+1 already applied.
// g_vg:   v,gate channels (original c in [1024,2048)), fp16 raw (bias applied).
__device__ float  g_qkvo[(size_t)NB * 1024 * NT];   // 134 MB fp32 (q,k elu'd)
__device__ __half g_vg  [(size_t)NB * 1024 * NT];   // 67 MB fp16 (v, gate)
__device__ __half g_lepe[(size_t)NB * CDIM * NT];   // 33 MB fp16
__device__ float  g_eff [NB * NHEADS * NT];
__device__ float  g_kv  [NB * NHEADS * HD * HD];
__device__ float  g_km  [NB * NHEADS * HD];
__device__ float  g_qm  [NB * NHEADS * HD];
// transposed rope tables [d][t] for coalesced access in kv/res
__device__ float  g_sint[HD * NT];                  // 1 MB
__device__ float  g_cost[HD * NT];                  // 1 MB

// fp16 operand buffers for tensor-core GEMMs (single product, pure fp16)
__device__ __half g_wqh[2048 * 512];
__device__ __half g_wph[512 * 512];
__device__ __half g_xth[(size_t)NB * NT * 512];
__device__ __half g_yth[(size_t)NB * NT * 512];

__device__ __forceinline__ float elu1(float x) { return x > 0.f ? x + 1.f : __expf(x); }

__device__ __forceinline__ float warpSum(float v) {
#pragma unroll
    for (int o = 16; o > 0; o >>= 1) v += __shfl_xor_sync(0xffffffffu, v, o);
    return v;
}
__device__ __forceinline__ float warpMax(float v) {
#pragma unroll
    for (int o = 16; o > 0; o >>= 1) v = fmaxf(v, __shfl_xor_sync(0xffffffffu, v, o));
    return v;
}

__device__ __forceinline__ uint32_t smem_u32(const void* p) {
    uint32_t a;
    asm("{ .reg .u64 t; cvta.to.shared.u64 t, %1; cvt.u32.u64 %0, t; }" : "=r"(a) : "l"(p));
    return a;
}
__device__ __forceinline__ void cp_async16(uint32_t dst, const void* src) {
    asm volatile("cp.async.cg.shared.global [%0], [%1], 16;" :: "r"(dst), "l"(src) : "memory");
}
__device__ __forceinline__ void cp_commit() {
    asm volatile("cp.async.commit_group;" ::: "memory");
}
template <int N>
__device__ __forceinline__ void cp_wait() {
    asm volatile("cp.async.wait_group %0;" :: "n"(N) : "memory");
}
__device__ __forceinline__ void ldsm_x4(uint32_t* r, uint32_t addr) {
    asm volatile("ldmatrix.sync.aligned.m8n8.x4.shared.b16 {%0,%1,%2,%3}, [%4];"
                 : "=r"(r[0]), "=r"(r[1]), "=r"(r[2]), "=r"(r[3]) : "r"(addr));
}
__device__ __forceinline__ void mma16816(float* d, const uint32_t* a, uint32_t b0, uint32_t b1) {
    asm volatile("mma.sync.aligned.m16n8k16.row.col.f32.f16.f16.f32 "
                 "{%0,%1,%2,%3}, {%4,%5,%6,%7}, {%8,%9}, {%0,%1,%2,%3};"
                 : "+f"(d[0]), "+f"(d[1]), "+f"(d[2]), "+f"(d[3])
                 : "r"(a[0]), "r"(a[1]), "r"(a[2]), "r"(a[3]), "r"(b0), "r"(b1));
}

// ---------------- zero accumulators (must run every graph replay) ----------------
__global__ void zero_kernel() {
    int i = blockIdx.x * blockDim.x + threadIdx.x;
    if (i < NB * NHEADS * HD * HD) g_kv[i] = 0.f;
    if (i < NB * NHEADS * HD) { g_km[i] = 0.f; g_qm[i] = 0.f; }
}

// ---------------- weight convert: fp32 -> fp16 ----------------
__global__ void wconv_kernel(const float* __restrict__ w, __half* __restrict__ wh, int n)
{
    int i = blockIdx.x * 256 + threadIdx.x;
    if (i < n) wh[i] = __float2half(w[i]);
}

// ---------------- sin/cos transpose: [t][d] -> [d][t] (coalesced rope reads) ----------------
__global__ void __launch_bounds__(256) scT_kernel(
    const float* __restrict__ sinp, const float* __restrict__ cosp)
{
    __shared__ float ts[32][33], tc[32][33];
    const int t0 = blockIdx.x * 32, d0 = blockIdx.y * 32;
    const int tx = threadIdx.x & 31, ty = threadIdx.x >> 5;   // 32x8
#pragma unroll
    for (int i = 0; i < 32; i += 8) {
        ts[ty + i][tx] = sinp[(size_t)(t0 + ty + i) * 64 + d0 + tx];
        tc[ty + i][tx] = cosp[(size_t)(t0 + ty + i) * 64 + d0 + tx];
    }
    __syncthreads();
#pragma unroll
    for (int i = 0; i < 32; i += 8) {
        g_sint[(size_t)(d0 + ty + i) * NT + t0 + tx] = ts[tx][ty + i];
        g_cost[(size_t)(d0 + ty + i) * NT + t0 + tx] = tc[tx][ty + i];
    }
}

// ---------------- transpose-convert: x[b][k][n] fp32 -> xT[b][n][k] fp16 ----------------
__global__ void __launch_bounds__(256) xpose_kernel(const float* __restrict__ x)
{
    const int b = blockIdx.z;
    const float* src = x + (size_t)b * 512 * NT;
    __half* dh = g_xth + (size_t)b * NT * 512;
    __shared__ float tile[32][33];
    const int n0 = blockIdx.x * 32, k0 = blockIdx.y * 32;
    const int tx = threadIdx.x & 31, ty = threadIdx.x >> 5; // 32x8
#pragma unroll
    for (int i = 0; i < 32; i += 8)
        tile[ty + i][tx] = src[(size_t)(k0 + ty + i) * NT + n0 + tx];
    __syncthreads();
#pragma unroll
    for (int i = 0; i < 32; i += 8) {
        size_t o = (size_t)(n0 + ty + i) * 512 + k0 + tx;
        dh[o] = __float2half(tile[tx][ty + i]);
    }
}

// ---------------- HMMA GEMM: C = A @ B^T + bias (BK=32, R11 best) ----------------
#define SROW 40
#define ARR_BYTES (128 * SROW * 2)     // 10240
#define STAGE_BYTES (2 * ARR_BYTES)    // 20480
#define GEMM_SMEM (2 * STAGE_BYTES)    // 40960

__global__ void __launch_bounds__(256, 2) gemm_hmma_kernel(
    const __half* __restrict__ Ah, const __half* __restrict__ Bh,
    const float* __restrict__ bias, float* __restrict__ C, __half* __restrict__ C16,
    int N, int elu_rows, int c16_start, int c_rows)
{
    const int b = blockIdx.z;
    const int m0 = blockIdx.y * 128, n0 = blockIdx.x * 128;
    const __half* pAh = Ah + (size_t)m0 * 512;
    const __half* pBh = Bh + ((size_t)b * N + n0) * 512;
    float*  Cb  = C   + (size_t)b * c_rows * N;   // fp32 rows [0, c16_start)
    __half* C16b = C16 ? C16 + (size_t)b * 1024 * N : (__half*)0;

    extern __shared__ char smem[];
    const uint32_t sb = smem_u32(smem);

    const int tid = threadIdx.x;
    const int lane = tid & 31, wid = tid >> 5;
    const int warp_m = wid & 3, warp_n = wid >> 2;   // 4 x 2 warps -> 32 x 64 per warp

    // cp.async mapping: thread -> (row, half)
    const int lrow = tid >> 1, lhalf = tid & 1;
    const size_t goff = (size_t)lrow * 512 + lhalf * 16;            // elements
    const uint32_t soff = (uint32_t)(lrow * SROW + lhalf * 16) * 2; // bytes

    // ldmatrix per-lane offsets (A and B both non-trans: SMEM is [row][k])
    const int arow = ((lane >> 3) & 1) * 8 + (lane & 7);   // = lane % 16
    const int acol = (lane >> 4) * 8;                      // k element offset
    const int brow = ((lane >> 4) & 1) * 8 + (lane & 7);   // n row within 16
    const int bcol = ((lane >> 3) & 1) * 8;                // k element offset

    float acc[2][8][4];
#pragma unroll
    for (int i = 0; i < 2; i++)
#pragma unroll
        for (int j = 0; j < 8; j++)
#pragma unroll
            for (int q = 0; q < 4; q++) acc[i][j][q] = 0.f;

    // prologue: stage 0
    {
        uint32_t d = sb + soff;
        cp_async16(d + 0 * ARR_BYTES, pAh + goff);
        cp_async16(d + 0 * ARR_BYTES + 16, pAh + goff + 8);
        cp_async16(d + 1 * ARR_BYTES, pBh + goff);
        cp_async16(d + 1 * ARR_BYTES + 16, pBh + goff + 8);
        cp_commit();
    }

    for (int c = 0; c < 16; c++) {
        cp_wait<0>();
        __syncthreads();

        if (c + 1 < 16) {     // issue next chunk; overlaps with compute of chunk c
            const size_t g = goff + (c + 1) * 32;
            uint32_t d = sb + ((c + 1) & 1) * STAGE_BYTES + soff;
            cp_async16(d + 0 * ARR_BYTES, pAh + g);
            cp_async16(d + 0 * ARR_BYTES + 16, pAh + g + 8);
            cp_async16(d + 1 * ARR_BYTES, pBh + g);
            cp_async16(d + 1 * ARR_BYTES + 16, pBh + g + 8);
            cp_commit();
        }

        const uint32_t st = sb + (c & 1) * STAGE_BYTES;
        const uint32_t aB  = st + 0 * ARR_BYTES;  // A
        const uint32_t bB  = st + 1 * ARR_BYTES;  // B

#pragma unroll
        for (int kk = 0; kk < 2; kk++) {
            uint32_t ah[2][4];
#pragma unroll
            for (int mt = 0; mt < 2; mt++) {
                uint32_t ao = (uint32_t)((warp_m * 32 + mt * 16 + arow) * SROW + kk * 16 + acol) * 2;
                ldsm_x4(ah[mt], aB + ao);
            }
#pragma unroll
            for (int g = 0; g < 4; g++) {
                uint32_t bo = (uint32_t)((warp_n * 64 + g * 16 + brow) * SROW + kk * 16 + bcol) * 2;
                uint32_t bh[4];
                ldsm_x4(bh, bB + bo);   // non-trans: SMEM already [n][k] (col-major B)
#pragma unroll
                for (int mt = 0; mt < 2; mt++) {
                    mma16816(acc[mt][g * 2 + 0], ah[mt], bh[0], bh[1]);
                    mma16816(acc[mt][g * 2 + 1], ah[mt], bh[2], bh[3]);
                }
            }
        }
        __syncthreads();   // protect stage (c&1) before it is re-filled at c+1
    }

    // epilogue: bias (+ fused elu + fused qmean) + fp32/fp16 stores
#pragma unroll
    for (int mt = 0; mt < 2; mt++) {
        int mA = m0 + warp_m * 32 + mt * 16 + (lane >> 2);
        int mB = mA + 8;
        float bv0 = bias[mA], bv1 = bias[mB];
        const bool e0r = mA < elu_rows, e1r = mB < elu_rows;
        const bool f0 = mA >= c16_start, f1 = mB >= c16_start;
        float*  r0f = Cb + (size_t)mA * N;
        float*  r1f = Cb + (size_t)mB * N;
        __half* r0h = f0 ? C16b + (size_t)(mA - c16_start) * N : (__half*)0;
        __half* r1h = f1 ? C16b + (size_t)(mB - c16_start) * N : (__half*)0;
        float qs0 = 0.f, qs1 = 0.f;
#pragma unroll
        for (int nt = 0; nt < 8; nt++) {
            int n = n0 + warp_n * 64 + nt * 8 + (lane & 3) * 2;
            float a0 = acc[mt][nt][0] + bv0, a1 = acc[mt][nt][1] + bv0;
            float a2 = acc[mt][nt][2] + bv1, a3 = acc[mt][nt][3] + bv1;
            if (e0r) { a0 = elu1(a0); a1 = elu1(a1); qs0 += a0 + a1; }
            if (e1r) { a2 = elu1(a2); a3 = elu1(a3); qs1 += a2 + a3; }
            if (f0) *(__half2*)(r0h + n) = __floats2half2_rn(a0, a1);
            else    *(float2*)(r0f + n) = make_float2(a0, a1);
            if (f1) *(__half2*)(r1h + n) = __floats2half2_rn(a2, a3);
            else    *(float2*)(r1f + n) = make_float2(a2, a3);
        }
        // fused qmean: q rows are m < 512 (only relevant for GEMM1, elu_rows > 0)
        if (elu_rows > 0 && mA < 512) {          // uniform across warp
            qs0 += __shfl_xor_sync(0xffffffffu, qs0, 1);
            qs0 += __shfl_xor_sync(0xffffffffu, qs0, 2);
            qs1 += __shfl_xor_sync(0xffffffffu, qs1, 1);
            qs1 += __shfl_xor_sync(0xffffffffu, qs1, 2);
            if ((lane & 3) == 0) {
                atomicAdd(&g_qm[(size_t)b * 512 + mA], qs0);
                atomicAdd(&g_qm[(size_t)b * 512 + mB], qs1);
            }
        }
    }
}

// ---------------- depthwise 5x5 conv on v channels (fp16) -> g_lepe (fp16) ----------------
__global__ void __launch_bounds__(256) conv_kernel(
    const float* __restrict__ w_lepe, const float* __restrict__ b_lepe)
{
    const int bc = blockIdx.x;
    const int b = bc >> 9, c = bc & 511;
    __shared__ float wsh[25];
    const int tid = threadIdx.x;
    if (tid < 25) wsh[tid] = w_lepe[c * 25 + tid];
    __syncthreads();

    const int y = blockIdx.y * 4 + (tid >> 6);
    const int xw = tid & 63;
    const __half* Vp = g_vg + ((size_t)b * 1024 + c) * NT;   // v channels = c' in [0,512)

    float acc = b_lepe[c];
#pragma unroll
    for (int i = 0; i < 5; i++) {
        int yy = y + i - 2;
        if (yy < 0 || yy >= 64) continue;
#pragma unroll
        for (int j = 0; j < 5; j++) {
            int xx = xw + j - 2;
            if (xx < 0 || xx >= 64) continue;
            acc += wsh[i * 5 + j] * __half2float(Vp[yy * 64 + xx]);
        }
    }
    g_lepe[((size_t)b * 512 + c) * NT + y * 64 + xw] = __float2half(acc);
}

// ---------------- logits -> softmax ----------------
__global__ void __launch_bounds__(256) logits_kernel()
{
    const int bh = blockIdx.x;
    const int b = bh >> 3, h = bh & 7;
    const float* Kp = g_qkvo + ((size_t)b * 1024 + 512 + h * 64) * NT;
    __shared__ float sq[64];
    const int tid = threadIdx.x;
    if (tid < 64) sq[tid] = g_qm[bh * 64 + tid] * (1.f / NT);
    __syncthreads();
    const int t = blockIdx.y * 256 + tid;
    float l = 0.f;
#pragma unroll 8
    for (int d = 0; d < 64; d++) l += sq[d] * Kp[(size_t)d * NT + t];
    g_eff[bh * NT + t] = l * 0.125f;   // SCALE
}

__global__ void __launch_bounds__(256) softmax_kernel()
{
    const int bh = blockIdx.x;
    const int tid = threadIdx.x;
    const int lane = tid & 31, wid = tid >> 5;
    __shared__ float red[8];
    float l[16];
#pragma unroll
    for (int i = 0; i < 16; i++) l[i] = g_eff[bh * NT + tid + i * 256];
    float mx = -1e30f;
#pragma unroll
    for (int i = 0; i < 16; i++) mx = fmaxf(mx, l[i]);
    mx = warpMax(mx);
    if (lane == 0) red[wid] = mx;
    __syncthreads();
    if (tid == 0) { float m = red[0]; for (int w = 1; w < 8; w++) m = fmaxf(m, red[w]); red[0] = m; }
    __syncthreads();
    mx = red[0];
    __syncthreads();
    float s = 0.f;
#pragma unroll
    for (int i = 0; i < 16; i++) s += __expf(l[i] - mx);
    s = warpSum(s);
    if (lane == 0) red[wid] = s;
    __syncthreads();
    if (tid == 0) { float ss = 0.f; for (int w = 0; w < 8; w++) ss += red[w]; red[0] = ss; }
    __syncthreads();
    const float inv = 1.f / red[0];
#pragma unroll
    for (int i = 0; i < 16; i++)
        g_eff[bh * NT + tid + i * 256] = __expf(l[i] - mx) * inv;
}

// ---------------- kv[d,e] = sum_t rope(k*eff)[t,d]*v[t,e];  km[d] = sum_t k*eff ----------------
// rope tables read from TRANSPOSED layout [d][t] -> coalesced.
__global__ void __launch_bounds__(256) kv_kernel()
{
    const int bh = blockIdx.x;
    const int b = bh >> 3, h = bh & 7;
    const int chunk = blockIdx.y;   // 16 chunks of 256 t
    const float*  Kp = g_qkvo + ((size_t)b * 1024 + 512 + h * 64) * NT;   // elu'd k
    const __half* Vp = g_vg   + ((size_t)b * 1024 + h * 64) * NT;         // v fp16
    const float* eff = g_eff + bh * NT;

    __shared__ float sk[64][65];   // rope(k*eff), [t][d]
    __shared__ float sv[64][65];   // v, [t][e]

    const int tid = threadIdx.x;
    const int ttl = tid & 63;
    const int drow = tid >> 6;     // 0..3
    const int d0 = (tid & 15) * 4, e0 = (tid >> 4) * 4;

    float acc[4][4];
#pragma unroll
    for (int i = 0; i < 4; i++)
#pragma unroll
        for (int j = 0; j < 4; j++) acc[i][j] = 0.f;
    float kmp[16];
#pragma unroll
    for (int i = 0; i < 16; i++) kmp[i] = 0.f;

    for (int tile = 0; tile < 4; tile++) {
        const int t = chunk * 256 + tile * 64 + ttl;
        const float effv = eff[t];
#pragma unroll
        for (int r = 0; r < 8; r++) {
            const int d = 2 * (drow + r * 4);
            float a  = Kp[(size_t)d * NT + t] * effv;
            float bb = Kp[(size_t)(d + 1) * NT + t] * effv;
            kmp[2 * r]     += a;
            kmp[2 * r + 1] += bb;
            float c0 = g_cost[(size_t)d * NT + t],       s0 = g_sint[(size_t)d * NT + t];
            float c1 = g_cost[(size_t)(d + 1) * NT + t], s1 = g_sint[(size_t)(d + 1) * NT + t];
            sk[ttl][d]     = a * c0 - bb * s0;
            sk[ttl][d + 1] = bb * c1 + a * s1;
            sv[ttl][d]     = __half2float(Vp[(size_t)d * NT + t]);
            sv[ttl][d + 1] = __half2float(Vp[(size_t)(d + 1) * NT + t]);
        }
        __syncthreads();

#pragma unroll 4
        for (int tt = 0; tt < 64; tt++) {
            float kk[4], vv[4];
#pragma unroll
            for (int j = 0; j < 4; j++) { kk[j] = sk[tt][d0 + j]; vv[j] = sv[tt][e0 + j]; }
#pragma unroll
            for (int i = 0; i < 4; i++)
#pragma unroll
                for (int j = 0; j < 4; j++) acc[i][j] += kk[i] * vv[j];
        }
        __syncthreads();
    }

    float* kvout = g_kv + (size_t)bh * HD * HD;
#pragma unroll
    for (int i = 0; i < 4; i++)
#pragma unroll
        for (int j = 0; j < 4; j++)
            atomicAdd(&kvout[(d0 + i) * 64 + e0 + j], acc[i][j]);

    // km reduction: stage register partials into sk, column-sum over t-slots
#pragma unroll
    for (int r = 0; r < 8; r++) {
        const int d = 2 * (drow + r * 4);
        sk[ttl][d]     = kmp[2 * r];
        sk[ttl][d + 1] = kmp[2 * r + 1];
    }
    __syncthreads();
    if (tid < 64) {
        float s = 0.f;
#pragma unroll 8
        for (int tt = 0; tt < 64; tt++) s += sk[tt][tid];
        atomicAdd(&g_km[bh * 64 + tid], s);
    }
}

// ---------------- res: y = (attn*z + lepe)*gate -> yT fp16 ----------------
// R14 compute form (1 t per thread). Output staged through SMEM so global
// stores are row-per-warp half2 (fully coalesced 128B lines) instead of
// per-thread scattered STG.16 (32 sectors/instr, 16x write amplification).
#define RES_SMEM (64 * 64 * 4 + 256 * 66 * 2 + 64 * 4)   // skv + ytile + skm = 50432

__global__ void __launch_bounds__(256) res_kernel()
{
    const int bh = blockIdx.x;
    const int b = bh >> 3, h = bh & 7;
    const int tid = threadIdx.x;
    const int t0 = blockIdx.y * 256;
    const int t = t0 + tid;
    const float* Q = g_qkvo + ((size_t)b * 1024 + h * 64) * NT;   // elu'd q

    extern __shared__ char rsm[];
    float*  skv   = (float*)rsm;                       // [64][64]
    __half* ytile = (__half*)(rsm + 64 * 64 * 4);      // [256][66] padded
    float*  skm   = (float*)(rsm + 64 * 64 * 4 + 256 * 66 * 2);  // [64]

#pragma unroll
    for (int r = 0; r < 16; r++)
        skv[tid + r * 256] = g_kv[(size_t)bh * 4096 + tid + r * 256];
    if (tid < 64) skm[tid] = g_km[bh * 64 + tid];
    __syncthreads();

    float res[64];
#pragma unroll
    for (int e = 0; e < 64; e++) res[e] = 0.f;
    float zacc = 0.f;

    for (int p = 0; p < 32; p++) {
        const int d = 2 * p;
        float q0 = Q[(size_t)d * NT + t];
        float q1 = Q[(size_t)(d + 1) * NT + t];
        zacc += q0 * skm[d] + q1 * skm[d + 1];
        float c0 = g_cost[(size_t)d * NT + t],       s0 = g_sint[(size_t)d * NT + t];
        float c1 = g_cost[(size_t)(d + 1) * NT + t], s1 = g_sint[(size_t)(d + 1) * NT + t];
        float qr0 = q0 * c0 - q1 * s0;
        float qr1 = q1 * c1 + q0 * s1;
        const float4* kv0 = (const float4*)(skv + d * 64);
        const float4* kv1 = (const float4*)(skv + (d + 1) * 64);
#pragma unroll
        for (int e4 = 0; e4 < 16; e4++) {
            float4 a = kv0[e4], bb = kv1[e4];
            res[e4 * 4 + 0] += qr0 * a.x + qr1 * bb.x;
            res[e4 * 4 + 1] += qr0 * a.y + qr1 * bb.y;
            res[e4 * 4 + 2] += qr0 * a.z + qr1 * bb.z;
            res[e4 * 4 + 3] += qr0 * a.w + qr1 * bb.w;
        }
    }
    const float z = 1.f / (zacc + 1e-6f);

    // gate/lepe loads stay coalesced (lanes span t); results go to SMEM tile
#pragma unroll 8
    for (int e2 = 0; e2 < 32; e2++) {
        int c = h * 64 + e2 * 2;
        const size_t gbase = ((size_t)b * 1024 + 512 + c) * NT;
        const size_t lbase = ((size_t)b * 512 + c) * NT;
        float g0 = __half2float(g_vg[gbase + t]);
        float l0 = __half2float(g_lepe[lbase + t]);
        float g1 = __half2float(g_vg[gbase + NT + t]);
        float l1 = __half2float(g_lepe[lbase + NT + t]);
        float y0 = (res[e2 * 2 + 0] * z + l0) * g0;
        float y1 = (res[e2 * 2 + 1] * z + l1) * g1;
        *(__half2*)&ytile[tid * 66 + e2 * 2] = __floats2half2_rn(y0, y1);
    }
    __syncthreads();

    // coalesced write-out: each warp stores one full t-row (64 halfs = 128B)
    {
        const int lane = tid & 31, w = tid >> 5;
#pragma unroll
        for (int r = 0; r < 32; r++) {
            int row = w + r * 8;
            __half2 v = *(__half2*)&ytile[row * 66 + lane * 2];
            *(__half2*)&g_yth[((size_t)b * NT + t0 + row) * 512 + h * 64 + lane * 2] = v;
        }
    }
}

// ---------------- launch (single stream; GEMM1 at profiled slot #4) ----------------
extern "C" void kernel_launch(void* const* d_in, const int* in_sizes, int n_in,
                              void* d_out, int out_size)
{
    const float* x      = (const float*)d_in[0];
    const float* sinp   = (const float*)d_in[1];
    const float* cosp   = (const float*)d_in[2];
    const float* w_qkvo = (const float*)d_in[3];
    const float* b_qkvo = (const float*)d_in[4];
    const float* w_lepe = (const float*)d_in[5];
    const float* b_lepe = (const float*)d_in[6];
    const float* w_proj = (const float*)d_in[7];
    const float* b_proj = (const float*)d_in[8];
    float* out = (float*)d_out;

    float *qkvo_p = nullptr;
    __half *vg_p, *wqh, *wph, *xth, *yth;
    cudaGetSymbolAddress((void**)&qkvo_p, g_qkvo);
    cudaGetSymbolAddress((void**)&vg_p,  g_vg);
    cudaGetSymbolAddress((void**)&wqh, g_wqh);
    cudaGetSymbolAddress((void**)&wph, g_wph);
    cudaGetSymbolAddress((void**)&xth, g_xth);
    cudaGetSymbolAddress((void**)&yth, g_yth);

    cudaFuncSetAttribute(gemm_hmma_kernel, cudaFuncAttributeMaxDynamicSharedMemorySize, GEMM_SMEM);
    cudaFuncSetAttribute(res_kernel, cudaFuncAttributeMaxDynamicSharedMemorySize, RES_SMEM);

    // launches 1-3 (profiler captures launch #4 = GEMM1)
    xpose_kernel<<<dim3(NT / 32, 512 / 32, NB), 256>>>(x);
    zero_kernel<<<(NB * NHEADS * HD * HD + 255) / 256, 256>>>();
    wconv_kernel<<<(2048 * 512 + 255) / 256, 256>>>(w_qkvo, wqh, 2048 * 512);

    // GEMM1 (launch #4): 2048 rows; m<1024 fp32+elu (q,k; qmean for m<512),
    // m>=1024 fp16 into g_vg (v, gate)
    gemm_hmma_kernel<<<dim3(NT / 128, 2048 / 128, NB), 256, GEMM_SMEM>>>(
        wqh, xth, b_qkvo, qkvo_p, vg_p, NT, 1024, 1024, 1024);

    scT_kernel<<<dim3(NT / 32, 2), 256>>>(sinp, cosp);   // rope tables -> [d][t]

    conv_kernel<<<dim3(NB * CDIM, 16), 256>>>(w_lepe, b_lepe);
    logits_kernel<<<dim3(NB * NHEADS, 16), 256>>>();
    softmax_kernel<<<NB * NHEADS, 256>>>();
    kv_kernel<<<dim3(NB * NHEADS, 16), 256>>>();
    res_kernel<<<dim3(NB * NHEADS, 16), 256, RES_SMEM>>>();

    wconv_kernel<<<(512 * 512 + 255) / 256, 256>>>(w_proj, wph, 512 * 512);

    // GEMM2: 512 rows, all fp32 to out; no elu/qmean/fp16
    gemm_hmma_kernel<<<dim3(NT / 128, 512 / 128, NB), 256, GEMM_SMEM>>>(
        wph, yth, b_proj, out, (__half*)0, NT, 0, 1 << 30, 512);
}

// round 17
// speedup vs baseline: 1.2905x; 1.0060x over previous
#include <cuda_runtime.h>
#include <cuda_fp16.h>
#include <cstdint>

#define NB 8
#define CDIM 512
#define NHEADS 8
#define HD 64
#define NT 4096           // H*W = 64*64

// ---------------- scratch (device globals: alloc-free) ----------------
// g_qk: q,k channels (c in [0,1024)), fp16, elu(.)+1 already applied.
// g_vg: v,gate channels (original c in [1024,2048)), fp16 raw (bias applied).
__device__ __half g_qk  [(size_t)NB * 1024 * NT];   // 67 MB fp16 (q,k elu'd)
__device__ __half g_vg  [(size_t)NB * 1024 * NT];   // 67 MB fp16 (v, gate)
__device__ __half g_lepe[(size_t)NB * CDIM * NT];   // 33 MB fp16
__device__ float  g_eff [NB * NHEADS * NT];
__device__ float  g_kv  [NB * NHEADS * HD * HD];
__device__ float  g_km  [NB * NHEADS * HD];
__device__ float  g_qm  [NB * NHEADS * HD];
// transposed rope tables [d][t] for coalesced access in kv/res
__device__ float  g_sint[HD * NT];                  // 1 MB
__device__ float  g_cost[HD * NT];                  // 1 MB

// fp16 operand buffers for tensor-core GEMMs (single product, pure fp16)
__device__ __half g_wqh[2048 * 512];
__device__ __half g_wph[512 * 512];
__device__ __half g_xth[(size_t)NB * NT * 512];
__device__ __half g_yth[(size_t)NB * NT * 512];

__device__ __forceinline__ float elu1(float x) { return x > 0.f ? x + 1.f : __expf(x); }

__device__ __forceinline__ float warpSum(float v) {
#pragma unroll
    for (int o = 16; o > 0; o >>= 1) v += __shfl_xor_sync(0xffffffffu, v, o);
    return v;
}
__device__ __forceinline__ float warpMax(float v) {
#pragma unroll
    for (int o = 16; o > 0; o >>= 1) v = fmaxf(v, __shfl_xor_sync(0xffffffffu, v, o));
    return v;
}

__device__ __forceinline__ uint32_t smem_u32(const void* p) {
    uint32_t a;
    asm("{ .reg .u64 t; cvta.to.shared.u64 t, %1; cvt.u32.u64 %0, t; }" : "=r"(a) : "l"(p));
    return a;
}
__device__ __forceinline__ void cp_async16(uint32_t dst, const void* src) {
    asm volatile("cp.async.cg.shared.global [%0], [%1], 16;" :: "r"(dst), "l"(src) : "memory");
}
__device__ __forceinline__ void cp_commit() {
    asm volatile("cp.async.commit_group;" ::: "memory");
}
template <int N>
__device__ __forceinline__ void cp_wait() {
    asm volatile("cp.async.wait_group %0;" :: "n"(N) : "memory");
}
__device__ __forceinline__ void ldsm_x4(uint32_t* r, uint32_t addr) {
    asm volatile("ldmatrix.sync.aligned.m8n8.x4.shared.b16 {%0,%1,%2,%3}, [%4];"
                 : "=r"(r[0]), "=r"(r[1]), "=r"(r[2]), "=r"(r[3]) : "r"(addr));
}
__device__ __forceinline__ void mma16816(float* d, const uint32_t* a, uint32_t b0, uint32_t b1) {
    asm volatile("mma.sync.aligned.m16n8k16.row.col.f32.f16.f16.f32 "
                 "{%0,%1,%2,%3}, {%4,%5,%6,%7}, {%8,%9}, {%0,%1,%2,%3};"
                 : "+f"(d[0]), "+f"(d[1]), "+f"(d[2]), "+f"(d[3])
                 : "r"(a[0]), "r"(a[1]), "r"(a[2]), "r"(a[3]), "r"(b0), "r"(b1));
}

// ---------------- zero accumulators (must run every graph replay) ----------------
__global__ void zero_kernel() {
    int i = blockIdx.x * blockDim.x + threadIdx.x;
    if (i < NB * NHEADS * HD * HD) g_kv[i] = 0.f;
    if (i < NB * NHEADS * HD) { g_km[i] = 0.f; g_qm[i] = 0.f; }
}

// ---------------- weight convert: fp32 -> fp16 ----------------
__global__ void wconv_kernel(const float* __restrict__ w, __half* __restrict__ wh, int n)
{
    int i = blockIdx.x * 256 + threadIdx.x;
    if (i < n) wh[i] = __float2half(w[i]);
}

// ---------------- sin/cos transpose: [t][d] -> [d][t] (coalesced rope reads) ----------------
__global__ void __launch_bounds__(256) scT_kernel(
    const float* __restrict__ sinp, const float* __restrict__ cosp)
{
    __shared__ float ts[32][33], tc[32][33];
    const int t0 = blockIdx.x * 32, d0 = blockIdx.y * 32;
    const int tx = threadIdx.x & 31, ty = threadIdx.x >> 5;   // 32x8
#pragma unroll
    for (int i = 0; i < 32; i += 8) {
        ts[ty + i][tx] = sinp[(size_t)(t0 + ty + i) * 64 + d0 + tx];
        tc[ty + i][tx] = cosp[(size_t)(t0 + ty + i) * 64 + d0 + tx];
    }
    __syncthreads();
#pragma unroll
    for (int i = 0; i < 32; i += 8) {
        g_sint[(size_t)(d0 + ty + i) * NT + t0 + tx] = ts[tx][ty + i];
        g_cost[(size_t)(d0 + ty + i) * NT + t0 + tx] = tc[tx][ty + i];
    }
}

// ---------------- transpose-convert: x[b][k][n] fp32 -> xT[b][n][k] fp16 ----------------
__global__ void __launch_bounds__(256) xpose_kernel(const float* __restrict__ x)
{
    const int b = blockIdx.z;
    const float* src = x + (size_t)b * 512 * NT;
    __half* dh = g_xth + (size_t)b * NT * 512;
    __shared__ float tile[32][33];
    const int n0 = blockIdx.x * 32, k0 = blockIdx.y * 32;
    const int tx = threadIdx.x & 31, ty = threadIdx.x >> 5; // 32x8
#pragma unroll
    for (int i = 0; i < 32; i += 8)
        tile[ty + i][tx] = src[(size_t)(k0 + ty + i) * NT + n0 + tx];
    __syncthreads();
#pragma unroll
    for (int i = 0; i < 32; i += 8) {
        size_t o = (size_t)(n0 + ty + i) * 512 + k0 + tx;
        dh[o] = __float2half(tile[tx][ty + i]);
    }
}

// ---------------- HMMA GEMM: C = A @ B^T + bias (BK=32) ----------------
// GEMM1 (Ca != 0): all rows stored fp16 — m<1024 (elu'd q,k) -> Ca, m>=1024 -> Cb.
//   elu(.)+1 fused for m < elu_rows; qmean atomics for m < 512.
// GEMM2 (Ca == 0): fp32 rows to C.
#define SROW 40
#define ARR_BYTES (128 * SROW * 2)     // 10240
#define STAGE_BYTES (2 * ARR_BYTES)    // 20480
#define GEMM_SMEM (2 * STAGE_BYTES)    // 40960

__global__ void __launch_bounds__(256, 2) gemm_hmma_kernel(
    const __half* __restrict__ Ah, const __half* __restrict__ Bh,
    const float* __restrict__ bias, float* __restrict__ C,
    __half* __restrict__ Ca, __half* __restrict__ Cb16,
    int N, int elu_rows)
{
    const int b = blockIdx.z;
    const int m0 = blockIdx.y * 128, n0 = blockIdx.x * 128;
    const __half* pAh = Ah + (size_t)m0 * 512;
    const __half* pBh = Bh + ((size_t)b * N + n0) * 512;
    float*  Cf  = C    ? C    + (size_t)b * 512 * N  : (float*)0;
    __half* CaB = Ca   ? Ca   + (size_t)b * 1024 * N : (__half*)0;
    __half* CbB = Cb16 ? Cb16 + (size_t)b * 1024 * N : (__half*)0;

    extern __shared__ char smem[];
    const uint32_t sb = smem_u32(smem);

    const int tid = threadIdx.x;
    const int lane = tid & 31, wid = tid >> 5;
    const int warp_m = wid & 3, warp_n = wid >> 2;   // 4 x 2 warps -> 32 x 64 per warp

    // cp.async mapping: thread -> (row, half)
    const int lrow = tid >> 1, lhalf = tid & 1;
    const size_t goff = (size_t)lrow * 512 + lhalf * 16;            // elements
    const uint32_t soff = (uint32_t)(lrow * SROW + lhalf * 16) * 2; // bytes

    // ldmatrix per-lane offsets (A and B both non-trans: SMEM is [row][k])
    const int arow = ((lane >> 3) & 1) * 8 + (lane & 7);   // = lane % 16
    const int acol = (lane >> 4) * 8;                      // k element offset
    const int brow = ((lane >> 4) & 1) * 8 + (lane & 7);   // n row within 16
    const int bcol = ((lane >> 3) & 1) * 8;                // k element offset

    float acc[2][8][4];
#pragma unroll
    for (int i = 0; i < 2; i++)
#pragma unroll
        for (int j = 0; j < 8; j++)
#pragma unroll
            for (int q = 0; q < 4; q++) acc[i][j][q] = 0.f;

    // prologue: stage 0
    {
        uint32_t d = sb + soff;
        cp_async16(d + 0 * ARR_BYTES, pAh + goff);
        cp_async16(d + 0 * ARR_BYTES + 16, pAh + goff + 8);
        cp_async16(d + 1 * ARR_BYTES, pBh + goff);
        cp_async16(d + 1 * ARR_BYTES + 16, pBh + goff + 8);
        cp_commit();
    }

    for (int c = 0; c < 16; c++) {
        cp_wait<0>();
        __syncthreads();

        if (c + 1 < 16) {     // issue next chunk; overlaps with compute of chunk c
            const size_t g = goff + (c + 1) * 32;
            uint32_t d = sb + ((c + 1) & 1) * STAGE_BYTES + soff;
            cp_async16(d + 0 * ARR_BYTES, pAh + g);
            cp_async16(d + 0 * ARR_BYTES + 16, pAh + g + 8);
            cp_async16(d + 1 * ARR_BYTES, pBh + g);
            cp_async16(d + 1 * ARR_BYTES + 16, pBh + g + 8);
            cp_commit();
        }

        const uint32_t st = sb + (c & 1) * STAGE_BYTES;
        const uint32_t aB  = st + 0 * ARR_BYTES;  // A
        const uint32_t bB  = st + 1 * ARR_BYTES;  // B

#pragma unroll
        for (int kk = 0; kk < 2; kk++) {
            uint32_t ah[2][4];
#pragma unroll
            for (int mt = 0; mt < 2; mt++) {
                uint32_t ao = (uint32_t)((warp_m * 32 + mt * 16 + arow) * SROW + kk * 16 + acol) * 2;
                ldsm_x4(ah[mt], aB + ao);
            }
#pragma unroll
            for (int g = 0; g < 4; g++) {
                uint32_t bo = (uint32_t)((warp_n * 64 + g * 16 + brow) * SROW + kk * 16 + bcol) * 2;
                uint32_t bh[4];
                ldsm_x4(bh, bB + bo);   // non-trans: SMEM already [n][k] (col-major B)
#pragma unroll
                for (int mt = 0; mt < 2; mt++) {
                    mma16816(acc[mt][g * 2 + 0], ah[mt], bh[0], bh[1]);
                    mma16816(acc[mt][g * 2 + 1], ah[mt], bh[2], bh[3]);
                }
            }
        }
        __syncthreads();   // protect stage (c&1) before it is re-filled at c+1
    }

    // epilogue: bias (+ fused elu + fused qmean) + stores
#pragma unroll
    for (int mt = 0; mt < 2; mt++) {
        int mA = m0 + warp_m * 32 + mt * 16 + (lane >> 2);
        int mB = mA + 8;
        float bv0 = bias[mA], bv1 = bias[mB];
        const bool e0r = mA < elu_rows, e1r = mB < elu_rows;
        __half* rh0 = CaB ? ((mA < 1024) ? CaB + (size_t)mA * N : CbB + (size_t)(mA - 1024) * N) : (__half*)0;
        __half* rh1 = CaB ? ((mB < 1024) ? CaB + (size_t)mB * N : CbB + (size_t)(mB - 1024) * N) : (__half*)0;
        float*  rf0 = Cf ? Cf + (size_t)mA * N : (float*)0;
        float*  rf1 = Cf ? Cf + (size_t)mB * N : (float*)0;
        float qs0 = 0.f, qs1 = 0.f;
#pragma unroll
        for (int nt = 0; nt < 8; nt++) {
            int n = n0 + warp_n * 64 + nt * 8 + (lane & 3) * 2;
            float a0 = acc[mt][nt][0] + bv0, a1 = acc[mt][nt][1] + bv0;
            float a2 = acc[mt][nt][2] + bv1, a3 = acc[mt][nt][3] + bv1;
            if (e0r) { a0 = elu1(a0); a1 = elu1(a1); qs0 += a0 + a1; }
            if (e1r) { a2 = elu1(a2); a3 = elu1(a3); qs1 += a2 + a3; }
            if (CaB) {
                *(__half2*)(rh0 + n) = __floats2half2_rn(a0, a1);
                *(__half2*)(rh1 + n) = __floats2half2_rn(a2, a3);
            } else {
                *(float2*)(rf0 + n) = make_float2(a0, a1);
                *(float2*)(rf1 + n) = make_float2(a2, a3);
            }
        }
        // fused qmean from pre-rounding fp32 values (q rows: m < 512)
        if (elu_rows > 0 && mA < 512) {          // uniform across warp
            qs0 += __shfl_xor_sync(0xffffffffu, qs0, 1);
            qs0 += __shfl_xor_sync(0xffffffffu, qs0, 2);
            qs1 += __shfl_xor_sync(0xffffffffu, qs1, 1);
            qs1 += __shfl_xor_sync(0xffffffffu, qs1, 2);
            if ((lane & 3) == 0) {
                atomicAdd(&g_qm[(size_t)b * 512 + mA], qs0);
                atomicAdd(&g_qm[(size_t)b * 512 + mB], qs1);
            }
        }
    }
}

// ---------------- depthwise 5x5 conv on v channels (fp16) -> g_lepe (fp16) ----------------
__global__ void __launch_bounds__(256) conv_kernel(
    const float* __restrict__ w_lepe, const float* __restrict__ b_lepe)
{
    const int bc = blockIdx.x;
    const int b = bc >> 9, c = bc & 511;
    __shared__ float wsh[25];
    const int tid = threadIdx.x;
    if (tid < 25) wsh[tid] = w_lepe[c * 25 + tid];
    __syncthreads();

    const int y = blockIdx.y * 4 + (tid >> 6);
    const int xw = tid & 63;
    const __half* Vp = g_vg + ((size_t)b * 1024 + c) * NT;   // v channels = c' in [0,512)

    float acc = b_lepe[c];
#pragma unroll
    for (int i = 0; i < 5; i++) {
        int yy = y + i - 2;
        if (yy < 0 || yy >= 64) continue;
#pragma unroll
        for (int j = 0; j < 5; j++) {
            int xx = xw + j - 2;
            if (xx < 0 || xx >= 64) continue;
            acc += wsh[i * 5 + j] * __half2float(Vp[yy * 64 + xx]);
        }
    }
    g_lepe[((size_t)b * 512 + c) * NT + y * 64 + xw] = __float2half(acc);
}

// ---------------- logits -> softmax ----------------
__global__ void __launch_bounds__(256) logits_kernel()
{
    const int bh = blockIdx.x;
    const int b = bh >> 3, h = bh & 7;
    const __half* Kp = g_qk + ((size_t)b * 1024 + 512 + h * 64) * NT;
    __shared__ float sq[64];
    const int tid = threadIdx.x;
    if (tid < 64) sq[tid] = g_qm[bh * 64 + tid] * (1.f / NT);
    __syncthreads();
    const int t = blockIdx.y * 256 + tid;
    float l = 0.f;
#pragma unroll 8
    for (int d = 0; d < 64; d++) l += sq[d] * __half2float(Kp[(size_t)d * NT + t]);
    g_eff[bh * NT + t] = l * 0.125f;   // SCALE
}

__global__ void __launch_bounds__(256) softmax_kernel()
{
    const int bh = blockIdx.x;
    const int tid = threadIdx.x;
    const int lane = tid & 31, wid = tid >> 5;
    __shared__ float red[8];
    float l[16];
#pragma unroll
    for (int i = 0; i < 16; i++) l[i] = g_eff[bh * NT + tid + i * 256];
    float mx = -1e30f;
#pragma unroll
    for (int i = 0; i < 16; i++) mx = fmaxf(mx, l[i]);
    mx = warpMax(mx);
    if (lane == 0) red[wid] = mx;
    __syncthreads();
    if (tid == 0) { float m = red[0]; for (int w = 1; w < 8; w++) m = fmaxf(m, red[w]); red[0] = m; }
    __syncthreads();
    mx = red[0];
    __syncthreads();
    float s = 0.f;
#pragma unroll
    for (int i = 0; i < 16; i++) s += __expf(l[i] - mx);
    s = warpSum(s);
    if (lane == 0) red[wid] = s;
    __syncthreads();
    if (tid == 0) { float ss = 0.f; for (int w = 0; w < 8; w++) ss += red[w]; red[0] = ss; }
    __syncthreads();
    const float inv = 1.f / red[0];
#pragma unroll
    for (int i = 0; i < 16; i++)
        g_eff[bh * NT + tid + i * 256] = __expf(l[i] - mx) * inv;
}

// ---------------- kv[d,e] = sum_t rope(k*eff)[t,d]*v[t,e];  km[d] = sum_t k*eff ----------------
// k fp16, rope tables transposed [d][t] -> all loads coalesced.
__global__ void __launch_bounds__(256) kv_kernel()
{
    const int bh = blockIdx.x;
    const int b = bh >> 3, h = bh & 7;
    const int chunk = blockIdx.y;   // 16 chunks of 256 t
    const __half* Kp = g_qk + ((size_t)b * 1024 + 512 + h * 64) * NT;   // elu'd k fp16
    const __half* Vp = g_vg + ((size_t)b * 1024 + h * 64) * NT;         // v fp16
    const float* eff = g_eff + bh * NT;

    __shared__ float sk[64][65];   // rope(k*eff), [t][d]
    __shared__ float sv[64][65];   // v, [t][e]

    const int tid = threadIdx.x;
    const int ttl = tid & 63;
    const int drow = tid >> 6;     // 0..3
    const int d0 = (tid & 15) * 4, e0 = (tid >> 4) * 4;

    float acc[4][4];
#pragma unroll
    for (int i = 0; i < 4; i++)
#pragma unroll
        for (int j = 0; j < 4; j++) acc[i][j] = 0.f;
    float kmp[16];
#pragma unroll
    for (int i = 0; i < 16; i++) kmp[i] = 0.f;

    for (int tile = 0; tile < 4; tile++) {
        const int t = chunk * 256 + tile * 64 + ttl;
        const float effv = eff[t];
#pragma unroll
        for (int r = 0; r < 8; r++) {
            const int d = 2 * (drow + r * 4);
            float a  = __half2float(Kp[(size_t)d * NT + t]) * effv;
            float bb = __half2float(Kp[(size_t)(d + 1) * NT + t]) * effv;
            kmp[2 * r]     += a;
            kmp[2 * r + 1] += bb;
            float c0 = g_cost[(size_t)d * NT + t],       s0 = g_sint[(size_t)d * NT + t];
            float c1 = g_cost[(size_t)(d + 1) * NT + t], s1 = g_sint[(size_t)(d + 1) * NT + t];
            sk[ttl][d]     = a * c0 - bb * s0;
            sk[ttl][d + 1] = bb * c1 + a * s1;
            sv[ttl][d]     = __half2float(Vp[(size_t)d * NT + t]);
            sv[ttl][d + 1] = __half2float(Vp[(size_t)(d + 1) * NT + t]);
        }
        __syncthreads();

#pragma unroll 4
        for (int tt = 0; tt < 64; tt++) {
            float kk[4], vv[4];
#pragma unroll
            for (int j = 0; j < 4; j++) { kk[j] = sk[tt][d0 + j]; vv[j] = sv[tt][e0 + j]; }
#pragma unroll
            for (int i = 0; i < 4; i++)
#pragma unroll
                for (int j = 0; j < 4; j++) acc[i][j] += kk[i] * vv[j];
        }
        __syncthreads();
    }

    float* kvout = g_kv + (size_t)bh * HD * HD;
#pragma unroll
    for (int i = 0; i < 4; i++)
#pragma unroll
        for (int j = 0; j < 4; j++)
            atomicAdd(&kvout[(d0 + i) * 64 + e0 + j], acc[i][j]);

    // km reduction: stage register partials into sk, column-sum over t-slots
#pragma unroll
    for (int r = 0; r < 8; r++) {
        const int d = 2 * (drow + r * 4);
        sk[ttl][d]     = kmp[2 * r];
        sk[ttl][d + 1] = kmp[2 * r + 1];
    }
    __syncthreads();
    if (tid < 64) {
        float s = 0.f;
#pragma unroll 8
        for (int tt = 0; tt < 64; tt++) s += sk[tt][tid];
        atomicAdd(&g_km[bh * 64 + tid], s);
    }
}

// ---------------- res: y = (attn*z + lepe)*gate -> yT fp16 ----------------
// 1 t per thread; q fp16; SMEM-staged coalesced output stores (R16).
#define RES_SMEM (64 * 64 * 4 + 256 * 66 * 2 + 64 * 4)   // skv + ytile + skm = 50432

__global__ void __launch_bounds__(256) res_kernel()
{
    const int bh = blockIdx.x;
    const int b = bh >> 3, h = bh & 7;
    const int tid = threadIdx.x;
    const int t0 = blockIdx.y * 256;
    const int t = t0 + tid;
    const __half* Q = g_qk + ((size_t)b * 1024 + h * 64) * NT;   // elu'd q fp16

    extern __shared__ char rsm[];
    float*  skv   = (float*)rsm;                       // [64][64]
    __half* ytile = (__half*)(rsm + 64 * 64 * 4);      // [256][66] padded
    float*  skm   = (float*)(rsm + 64 * 64 * 4 + 256 * 66 * 2);  // [64]

#pragma unroll
    for (int r = 0; r < 16; r++)
        skv[tid + r * 256] = g_kv[(size_t)bh * 4096 + tid + r * 256];
    if (tid < 64) skm[tid] = g_km[bh * 64 + tid];
    __syncthreads();

    float res[64];
#pragma unroll
    for (int e = 0; e < 64; e++) res[e] = 0.f;
    float zacc = 0.f;

    for (int p = 0; p < 32; p++) {
        const int d = 2 * p;
        float q0 = __half2float(Q[(size_t)d * NT + t]);
        float q1 = __half2float(Q[(size_t)(d + 1) * NT + t]);
        zacc += q0 * skm[d] + q1 * skm[d + 1];
        float c0 = g_cost[(size_t)d * NT + t],       s0 = g_sint[(size_t)d * NT + t];
        float c1 = g_cost[(size_t)(d + 1) * NT + t], s1 = g_sint[(size_t)(d + 1) * NT + t];
        float qr0 = q0 * c0 - q1 * s0;
        float qr1 = q1 * c1 + q0 * s1;
        const float4* kv0 = (const float4*)(skv + d * 64);
        const float4* kv1 = (const float4*)(skv + (d + 1) * 64);
#pragma unroll
        for (int e4 = 0; e4 < 16; e4++) {
            float4 a = kv0[e4], bb = kv1[e4];
            res[e4 * 4 + 0] += qr0 * a.x + qr1 * bb.x;
            res[e4 * 4 + 1] += qr0 * a.y + qr1 * bb.y;
            res[e4 * 4 + 2] += qr0 * a.z + qr1 * bb.z;
            res[e4 * 4 + 3] += qr0 * a.w + qr1 * bb.w;
        }
    }
    const float z = 1.f / (zacc + 1e-6f);

    // gate/lepe loads stay coalesced (lanes span t); results go to SMEM tile
#pragma unroll 8
    for (int e2 = 0; e2 < 32; e2++) {
        int c = h * 64 + e2 * 2;
        const size_t gbase = ((size_t)b * 1024 + 512 + c) * NT;
        const size_t lbase = ((size_t)b * 512 + c) * NT;
        float g0 = __half2float(g_vg[gbase + t]);
        float l0 = __half2float(g_lepe[lbase + t]);
        float g1 = __half2float(g_vg[gbase + NT + t]);
        float l1 = __half2float(g_lepe[lbase + NT + t]);
        float y0 = (res[e2 * 2 + 0] * z + l0) * g0;
        float y1 = (res[e2 * 2 + 1] * z + l1) * g1;
        *(__half2*)&ytile[tid * 66 + e2 * 2] = __floats2half2_rn(y0, y1);
    }
    __syncthreads();

    // coalesced write-out: each warp stores one full t-row (64 halfs = 128B)
    {
        const int lane = tid & 31, w = tid >> 5;
#pragma unroll
        for (int r = 0; r < 32; r++) {
            int row = w + r * 8;
            __half2 v = *(__half2*)&ytile[row * 66 + lane * 2];
            *(__half2*)&g_yth[((size_t)b * NT + t0 + row) * 512 + h * 64 + lane * 2] = v;
        }
    }
}

// ---------------- launch (single stream; GEMM1 at profiled slot #4) ----------------
extern "C" void kernel_launch(void* const* d_in, const int* in_sizes, int n_in,
                              void* d_out, int out_size)
{
    const float* x      = (const float*)d_in[0];
    const float* sinp   = (const float*)d_in[1];
    const float* cosp   = (const float*)d_in[2];
    const float* w_qkvo = (const float*)d_in[3];
    const float* b_qkvo = (const float*)d_in[4];
    const float* w_lepe = (const float*)d_in[5];
    const float* b_lepe = (const float*)d_in[6];
    const float* w_proj = (const float*)d_in[7];
    const float* b_proj = (const float*)d_in[8];
    float* out = (float*)d_out;

    __half *qk_p, *vg_p, *wqh, *wph, *xth, *yth;
    cudaGetSymbolAddress((void**)&qk_p, g_qk);
    cudaGetSymbolAddress((void**)&vg_p, g_vg);
    cudaGetSymbolAddress((void**)&wqh, g_wqh);
    cudaGetSymbolAddress((void**)&wph, g_wph);
    cudaGetSymbolAddress((void**)&xth, g_xth);
    cudaGetSymbolAddress((void**)&yth, g_yth);

    cudaFuncSetAttribute(gemm_hmma_kernel, cudaFuncAttributeMaxDynamicSharedMemorySize, GEMM_SMEM);
    cudaFuncSetAttribute(res_kernel, cudaFuncAttributeMaxDynamicSharedMemorySize, RES_SMEM);

    // launches 1-3 (profiler captures launch #4 = GEMM1)
    xpose_kernel<<<dim3(NT / 32, 512 / 32, NB), 256>>>(x);
    zero_kernel<<<(NB * NHEADS * HD * HD + 255) / 256, 256>>>();
    wconv_kernel<<<(2048 * 512 + 255) / 256, 256>>>(w_qkvo, wqh, 2048 * 512);

    // GEMM1 (launch #4): 2048 rows all fp16 out; m<1024 elu'd q,k -> g_qk
    // (qmean for m<512), m>=1024 raw v,gate -> g_vg
    gemm_hmma_kernel<<<dim3(NT / 128, 2048 / 128, NB), 256, GEMM_SMEM>>>(
        wqh, xth, b_qkvo, (float*)0, qk_p, vg_p, NT, 1024);

    scT_kernel<<<dim3(NT / 32, 2), 256>>>(sinp, cosp);   // rope tables -> [d][t]

    conv_kernel<<<dim3(NB * CDIM, 16), 256>>>(w_lepe, b_lepe);
    logits_kernel<<<dim3(NB * NHEADS, 16), 256>>>();
    softmax_kernel<<<NB * NHEADS, 256>>>();
    kv_kernel<<<dim3(NB * NHEADS, 16), 256>>>();
    res_kernel<<<dim3(NB * NHEADS, 16), 256, RES_SMEM>>>();

    wconv_kernel<<<(512 * 512 + 255) / 256, 256>>>(w_proj, wph, 512 * 512);

    // GEMM2: 512 rows fp32 to out; no elu/qmean
    gemm_hmma_kernel<<<dim3(NT / 128, 512 / 128, NB), 256, GEMM_SMEM>>>(
        wph, yth, b_proj, out, (__half*)0, (__half*)0, NT, 0);
}